// round 1
// baseline (speedup 1.0000x reference)
#include <cuda_runtime.h>
#include <cuda_bf16.h>
#include <cstddef>

// Problem constants
#define B_   4
#define TQ_  512
#define TP_  512
#define D_   256

// ---------------------------------------------------------------------------
// Scratch (static device globals -- no dynamic allocation allowed)
// ---------------------------------------------------------------------------
__device__ float g_pq[(size_t)B_ * TQ_ * D_];   // q @ W0   [B,Tq,D]
__device__ float g_pp[(size_t)B_ * TP_ * D_];   // p @ W1   [B,Tp,D]
__device__ float g_sc[(size_t)B_ * TP_ * TQ_];  // scores / weights [B,Tp,Tq]

// ---------------------------------------------------------------------------
// Fast, accurate tanh: tanh(x) = sign(x) * (1 - e) / (1 + e), e = exp(-2|x|)
// 2 MUFU (EX2, RCP) + ~5 fma/alu ops. Error ~2 ulp of __expf -> ~1e-6.
// Never overflows (argument <= 0).
// ---------------------------------------------------------------------------
__device__ __forceinline__ float ftanh(float x) {
    float e = __expf(-2.0f * fabsf(x));
    float r = __fdividef(1.0f - e, 1.0f + e);
    return copysignf(r, x);
}

// ---------------------------------------------------------------------------
// Generic register-tiled SGEMM: C[M,N] = A[M,K] * B[K,N], row-major fp32.
// 256 threads. All dims assumed divisible by block tiles.
// ---------------------------------------------------------------------------
template <int BM, int BN, int BK, int TM, int TN>
__device__ __forceinline__ void gemm_tile(const float* __restrict__ A,
                                          const float* __restrict__ B,
                                          float* __restrict__ C,
                                          int M, int N, int K) {
    constexpr int THREADS = (BM / TM) * (BN / TN);  // = 256
    __shared__ float As[BK][BM];  // transposed A tile
    __shared__ float Bs[BK][BN];

    const int tid = threadIdx.x;
    const int tnx = BN / TN;
    const int tx = tid % tnx;
    const int ty = tid / tnx;
    const int m0 = blockIdx.y * BM;
    const int n0 = blockIdx.x * BN;

    float acc[TM][TN];
#pragma unroll
    for (int i = 0; i < TM; i++)
#pragma unroll
        for (int j = 0; j < TN; j++) acc[i][j] = 0.0f;

    constexpr int A4 = BM * BK / (THREADS * 4);  // float4 loads per thread (A)
    constexpr int B4 = BN * BK / (THREADS * 4);  // float4 loads per thread (B)

    for (int k0 = 0; k0 < K; k0 += BK) {
#pragma unroll
        for (int s = 0; s < A4; s++) {
            int id = tid + s * THREADS;
            int r = id / (BK / 4);
            int c = (id % (BK / 4)) * 4;
            float4 av = *(const float4*)&A[(size_t)(m0 + r) * K + k0 + c];
            As[c + 0][r] = av.x;
            As[c + 1][r] = av.y;
            As[c + 2][r] = av.z;
            As[c + 3][r] = av.w;
        }
#pragma unroll
        for (int s = 0; s < B4; s++) {
            int id = tid + s * THREADS;
            int r = id / (BN / 4);
            int c = (id % (BN / 4)) * 4;
            *(float4*)&Bs[r][c] = *(const float4*)&B[(size_t)(k0 + r) * N + n0 + c];
        }
        __syncthreads();

#pragma unroll
        for (int k = 0; k < BK; k++) {
            float a[TM], bb[TN];
#pragma unroll
            for (int i = 0; i < TM; i++) a[i] = As[k][ty * TM + i];
#pragma unroll
            for (int j = 0; j < TN; j++) bb[j] = Bs[k][tx * TN + j];
#pragma unroll
            for (int i = 0; i < TM; i++)
#pragma unroll
                for (int j = 0; j < TN; j++)
                    acc[i][j] = fmaf(a[i], bb[j], acc[i][j]);
        }
        __syncthreads();
    }

#pragma unroll
    for (int i = 0; i < TM; i++) {
#pragma unroll
        for (int j = 0; j < TN; j += 4) {
            float4 o = make_float4(acc[i][j], acc[i][j + 1], acc[i][j + 2],
                                   acc[i][j + 3]);
            *(float4*)&C[(size_t)(m0 + ty * TM + i) * N + n0 + tx * TN + j] = o;
        }
    }
}

// ---------------------------------------------------------------------------
// Kernel 1: both projections in one launch (grid.z selects q/W0 vs p/W1)
//   g_pq = q @ W0  (M=2048, N=256, K=256);  g_pp = p @ W1
// ---------------------------------------------------------------------------
__global__ __launch_bounds__(256) void proj_kernel(const float* __restrict__ q,
                                                   const float* __restrict__ p,
                                                   const float* __restrict__ W0,
                                                   const float* __restrict__ W1) {
    const float* A = (blockIdx.z == 0) ? q : p;
    const float* Bw = (blockIdx.z == 0) ? W0 : W1;
    float* C = (blockIdx.z == 0) ? g_pq : g_pp;
    gemm_tile<128, 64, 16, 8, 4>(A, Bw, C, B_ * TQ_, D_, D_);
}

// ---------------------------------------------------------------------------
// Kernel 2: energies + vc reduction (the MUFU-bound heavy kernel)
//   g_sc[b,p,q] = sum_d vc[d] * tanh(g_pp[b,p,d] + g_pq[b,q,d])
// 32x32 score tile per block, 256 threads, 2x2 micro-tile per thread,
// D chunked by 64 through shared memory.
// ---------------------------------------------------------------------------
__global__ __launch_bounds__(256) void energy_kernel(const float* __restrict__ vc) {
    __shared__ float sp[32][68];  // +4 pad: keeps float4 alignment, breaks conflicts
    __shared__ float sq[32][68];
    __shared__ float sv[64];

    const int b = blockIdx.z;
    const int p0 = blockIdx.y * 32;
    const int q0 = blockIdx.x * 32;
    const int tid = threadIdx.x;
    const int tx = tid & 15;
    const int ty = tid >> 4;

    const float* ppb = g_pp + ((size_t)b * TP_ + p0) * D_;
    const float* pqb = g_pq + ((size_t)b * TQ_ + q0) * D_;

    float acc00 = 0.f, acc01 = 0.f, acc10 = 0.f, acc11 = 0.f;

    const int vr = tid >> 2;         // 0..63 : virtual row (32 pp + 32 pq)
    const int cb = (tid & 3) * 16;   // 16-float slab within the 64-wide row

    for (int d0 = 0; d0 < D_; d0 += 64) {
        if (tid < 64) sv[tid] = vc[d0 + tid];
        const float* src = (vr < 32) ? (ppb + (size_t)vr * D_ + d0)
                                     : (pqb + (size_t)(vr - 32) * D_ + d0);
        float* dst = (vr < 32) ? &sp[vr][0] : &sq[vr - 32][0];
#pragma unroll
        for (int j = 0; j < 16; j += 4)
            *(float4*)&dst[cb + j] = *(const float4*)&src[cb + j];
        __syncthreads();

#pragma unroll 2
        for (int d = 0; d < 64; d += 4) {
            float4 A0 = *(float4*)&sp[ty][d];
            float4 A1 = *(float4*)&sp[ty + 16][d];
            float4 B0 = *(float4*)&sq[tx][d];
            float4 B1 = *(float4*)&sq[tx + 16][d];
            float4 V = *(float4*)&sv[d];

            acc00 = fmaf(V.x, ftanh(A0.x + B0.x), acc00);
            acc01 = fmaf(V.x, ftanh(A0.x + B1.x), acc01);
            acc10 = fmaf(V.x, ftanh(A1.x + B0.x), acc10);
            acc11 = fmaf(V.x, ftanh(A1.x + B1.x), acc11);

            acc00 = fmaf(V.y, ftanh(A0.y + B0.y), acc00);
            acc01 = fmaf(V.y, ftanh(A0.y + B1.y), acc01);
            acc10 = fmaf(V.y, ftanh(A1.y + B0.y), acc10);
            acc11 = fmaf(V.y, ftanh(A1.y + B1.y), acc11);

            acc00 = fmaf(V.z, ftanh(A0.z + B0.z), acc00);
            acc01 = fmaf(V.z, ftanh(A0.z + B1.z), acc01);
            acc10 = fmaf(V.z, ftanh(A1.z + B0.z), acc10);
            acc11 = fmaf(V.z, ftanh(A1.z + B1.z), acc11);

            acc00 = fmaf(V.w, ftanh(A0.w + B0.w), acc00);
            acc01 = fmaf(V.w, ftanh(A0.w + B1.w), acc01);
            acc10 = fmaf(V.w, ftanh(A1.w + B0.w), acc10);
            acc11 = fmaf(V.w, ftanh(A1.w + B1.w), acc11);
        }
        __syncthreads();
    }

    const size_t base = ((size_t)b * TP_ + p0) * TQ_ + q0;
    g_sc[base + (size_t)ty * TQ_ + tx] = acc00;
    g_sc[base + (size_t)ty * TQ_ + tx + 16] = acc01;
    g_sc[base + (size_t)(ty + 16) * TQ_ + tx] = acc10;
    g_sc[base + (size_t)(ty + 16) * TQ_ + tx + 16] = acc11;
}

// ---------------------------------------------------------------------------
// Kernel 3: softmax over the p axis (axis=1 of [B,Tp,Tq]) -- column softmax.
// One thread per (b, q) column; accesses coalesced across threads.
// ---------------------------------------------------------------------------
__global__ __launch_bounds__(256) void softmax_kernel() {
    const int b = blockIdx.y;
    const int q = blockIdx.x * blockDim.x + threadIdx.x;
    float* s = g_sc + (size_t)b * TP_ * TQ_ + q;

    float m = -1e30f;
#pragma unroll 8
    for (int p = 0; p < TP_; p++) m = fmaxf(m, s[(size_t)p * TQ_]);

    float sum = 0.f;
#pragma unroll 8
    for (int p = 0; p < TP_; p++) {
        float e = __expf(s[(size_t)p * TQ_] - m);
        s[(size_t)p * TQ_] = e;
        sum += e;
    }

    float inv = __fdividef(1.0f, sum);
#pragma unroll 8
    for (int p = 0; p < TP_; p++) s[(size_t)p * TQ_] *= inv;
}

// ---------------------------------------------------------------------------
// Kernel 4: out[b,p,d] = sum_q weights[b,p,q] * q[b,q,d]
// Batched SGEMM: per-b  [Tp,Tq] x [Tq,D]
// ---------------------------------------------------------------------------
__global__ __launch_bounds__(256) void out_gemm_kernel(const float* __restrict__ qin,
                                                       float* __restrict__ out) {
    const int b = blockIdx.z;
    gemm_tile<64, 64, 16, 4, 4>(g_sc + (size_t)b * TP_ * TQ_,
                                qin + (size_t)b * TQ_ * D_,
                                out + (size_t)b * TP_ * D_, TP_, D_, TQ_);
}

// ---------------------------------------------------------------------------
// Launch
// ---------------------------------------------------------------------------
extern "C" void kernel_launch(void* const* d_in, const int* in_sizes, int n_in,
                              void* d_out, int out_size) {
    const float* q = (const float*)d_in[0];   // [B,Tq,D]
    const float* p = (const float*)d_in[1];   // [B,Tp,D]
    const float* W0 = (const float*)d_in[2];  // [D,D]
    const float* W1 = (const float*)d_in[3];  // [D,D]
    const float* vc = (const float*)d_in[4];  // [D,1]
    float* out = (float*)d_out;               // [B,Tp,D]

    // 1. Projections: g_pq = q@W0, g_pp = p@W1  (one launch, z selects)
    {
        dim3 grid(D_ / 64, (B_ * TQ_) / 128, 2);
        proj_kernel<<<grid, 256>>>(q, p, W0, W1);
    }
    // 2. Energies + vc reduction
    {
        dim3 grid(TQ_ / 32, TP_ / 32, B_);
        energy_kernel<<<grid, 256>>>(vc);
    }
    // 3. Column softmax over p
    {
        dim3 grid(TQ_ / 256, B_);
        softmax_kernel<<<grid, 256>>>();
    }
    // 4. Output GEMM
    {
        dim3 grid(D_ / 64, TP_ / 64, B_);
        out_gemm_kernel<<<grid, 256>>>(q, out);
    }
}

// round 2
// speedup vs baseline: 1.2648x; 1.2648x over previous
#include <cuda_runtime.h>
#include <cuda_bf16.h>
#include <cstddef>

// Problem constants
#define B_   4
#define TQ_  512
#define TP_  512
#define D_   256

// ---------------------------------------------------------------------------
// Scratch (static device globals -- no dynamic allocation allowed)
// ---------------------------------------------------------------------------
__device__ float g_pq[(size_t)B_ * TQ_ * D_];   // q @ W0   [B,Tq,D]
__device__ float g_pp[(size_t)B_ * TP_ * D_];   // p @ W1   [B,Tp,D]
__device__ float g_sc[(size_t)B_ * TP_ * TQ_];  // scores / weights [B,Tp,Tq]

// ---------------------------------------------------------------------------
// HW tanh: single MUFU.TANH (sm_75+). Abs err ~2e-4, halves MUFU pressure
// vs the exp-based formulation (which needed EX2 + RCP).
// ---------------------------------------------------------------------------
__device__ __forceinline__ float ftanh(float x) {
    float r;
    asm("tanh.approx.f32 %0, %1;" : "=f"(r) : "f"(x));
    return r;
}

// ---------------------------------------------------------------------------
// Generic register-tiled SGEMM: C[M,N] = A[M,K] * B[K,N], row-major fp32.
// 256 threads. All dims assumed divisible by block tiles.
// ---------------------------------------------------------------------------
template <int BM, int BN, int BK, int TM, int TN>
__device__ __forceinline__ void gemm_tile(const float* __restrict__ A,
                                          const float* __restrict__ B,
                                          float* __restrict__ C,
                                          int M, int N, int K) {
    constexpr int THREADS = (BM / TM) * (BN / TN);  // = 256
    __shared__ float As[BK][BM];  // transposed A tile
    __shared__ float Bs[BK][BN];

    const int tid = threadIdx.x;
    const int tnx = BN / TN;
    const int tx = tid % tnx;
    const int ty = tid / tnx;
    const int m0 = blockIdx.y * BM;
    const int n0 = blockIdx.x * BN;

    float acc[TM][TN];
#pragma unroll
    for (int i = 0; i < TM; i++)
#pragma unroll
        for (int j = 0; j < TN; j++) acc[i][j] = 0.0f;

    constexpr int A4 = BM * BK / (THREADS * 4);  // float4 loads per thread (A)
    constexpr int B4 = BN * BK / (THREADS * 4);  // float4 loads per thread (B)
    static_assert(A4 >= 1 && B4 >= 1, "tile too small for loader");

    for (int k0 = 0; k0 < K; k0 += BK) {
#pragma unroll
        for (int s = 0; s < A4; s++) {
            int id = tid + s * THREADS;
            int r = id / (BK / 4);
            int c = (id % (BK / 4)) * 4;
            float4 av = *(const float4*)&A[(size_t)(m0 + r) * K + k0 + c];
            As[c + 0][r] = av.x;
            As[c + 1][r] = av.y;
            As[c + 2][r] = av.z;
            As[c + 3][r] = av.w;
        }
#pragma unroll
        for (int s = 0; s < B4; s++) {
            int id = tid + s * THREADS;
            int r = id / (BN / 4);
            int c = (id % (BN / 4)) * 4;
            *(float4*)&Bs[r][c] = *(const float4*)&B[(size_t)(k0 + r) * N + n0 + c];
        }
        __syncthreads();

#pragma unroll
        for (int k = 0; k < BK; k++) {
            float a[TM], bb[TN];
#pragma unroll
            for (int i = 0; i < TM; i++) a[i] = As[k][ty * TM + i];
#pragma unroll
            for (int j = 0; j < TN; j++) bb[j] = Bs[k][tx * TN + j];
#pragma unroll
            for (int i = 0; i < TM; i++)
#pragma unroll
                for (int j = 0; j < TN; j++)
                    acc[i][j] = fmaf(a[i], bb[j], acc[i][j]);
        }
        __syncthreads();
    }

#pragma unroll
    for (int i = 0; i < TM; i++) {
#pragma unroll
        for (int j = 0; j < TN; j += 2) {
            if constexpr (TN >= 4 && TN % 4 == 0) {
                if (j % 4 == 0) {
                    float4 o = make_float4(acc[i][j], acc[i][j + 1],
                                           acc[i][j + 2], acc[i][j + 3]);
                    *(float4*)&C[(size_t)(m0 + ty * TM + i) * N + n0 + tx * TN + j] = o;
                }
            } else {
                float2 o = make_float2(acc[i][j], acc[i][j + 1]);
                *(float2*)&C[(size_t)(m0 + ty * TM + i) * N + n0 + tx * TN + j] = o;
            }
        }
    }
}

// ---------------------------------------------------------------------------
// Kernel 1: both projections in one launch (grid.z selects q/W0 vs p/W1)
//   g_pq = q @ W0  (M=2048, N=256, K=256);  g_pp = p @ W1
// 64x64 tiles -> 256 blocks (was 128) for 2x residency.
// ---------------------------------------------------------------------------
__global__ __launch_bounds__(256) void proj_kernel(const float* __restrict__ q,
                                                   const float* __restrict__ p,
                                                   const float* __restrict__ W0,
                                                   const float* __restrict__ W1) {
    const float* A = (blockIdx.z == 0) ? q : p;
    const float* Bw = (blockIdx.z == 0) ? W0 : W1;
    float* C = (blockIdx.z == 0) ? g_pq : g_pp;
    gemm_tile<64, 64, 16, 4, 4>(A, Bw, C, B_ * TQ_, D_, D_);
}

// ---------------------------------------------------------------------------
// Kernel 2: energies + vc reduction (the MUFU-bound heavy kernel)
//   g_sc[b,p,q] = sum_d vc[d] * tanh(g_pp[b,p,d] + g_pq[b,q,d])
// 32x32 score tile per block, 256 threads, 2x2 micro-tile per thread,
// D chunked by 64 through shared memory.
// ---------------------------------------------------------------------------
__global__ __launch_bounds__(256) void energy_kernel(const float* __restrict__ vc) {
    __shared__ float sp[32][68];  // +4 pad: keeps float4 alignment, breaks conflicts
    __shared__ float sq[32][68];
    __shared__ float sv[64];

    const int b = blockIdx.z;
    const int p0 = blockIdx.y * 32;
    const int q0 = blockIdx.x * 32;
    const int tid = threadIdx.x;
    const int tx = tid & 15;
    const int ty = tid >> 4;

    const float* ppb = g_pp + ((size_t)b * TP_ + p0) * D_;
    const float* pqb = g_pq + ((size_t)b * TQ_ + q0) * D_;

    float acc00 = 0.f, acc01 = 0.f, acc10 = 0.f, acc11 = 0.f;

    const int vr = tid >> 2;         // 0..63 : virtual row (32 pp + 32 pq)
    const int cb = (tid & 3) * 16;   // 16-float slab within the 64-wide row

    for (int d0 = 0; d0 < D_; d0 += 64) {
        if (tid < 64) sv[tid] = vc[d0 + tid];
        const float* src = (vr < 32) ? (ppb + (size_t)vr * D_ + d0)
                                     : (pqb + (size_t)(vr - 32) * D_ + d0);
        float* dst = (vr < 32) ? &sp[vr][0] : &sq[vr - 32][0];
#pragma unroll
        for (int j = 0; j < 16; j += 4)
            *(float4*)&dst[cb + j] = *(const float4*)&src[cb + j];
        __syncthreads();

#pragma unroll 2
        for (int d = 0; d < 64; d += 4) {
            float4 A0 = *(float4*)&sp[ty][d];
            float4 A1 = *(float4*)&sp[ty + 16][d];
            float4 B0 = *(float4*)&sq[tx][d];
            float4 B1 = *(float4*)&sq[tx + 16][d];
            float4 V = *(float4*)&sv[d];

            acc00 = fmaf(V.x, ftanh(A0.x + B0.x), acc00);
            acc01 = fmaf(V.x, ftanh(A0.x + B1.x), acc01);
            acc10 = fmaf(V.x, ftanh(A1.x + B0.x), acc10);
            acc11 = fmaf(V.x, ftanh(A1.x + B1.x), acc11);

            acc00 = fmaf(V.y, ftanh(A0.y + B0.y), acc00);
            acc01 = fmaf(V.y, ftanh(A0.y + B1.y), acc01);
            acc10 = fmaf(V.y, ftanh(A1.y + B0.y), acc10);
            acc11 = fmaf(V.y, ftanh(A1.y + B1.y), acc11);

            acc00 = fmaf(V.z, ftanh(A0.z + B0.z), acc00);
            acc01 = fmaf(V.z, ftanh(A0.z + B1.z), acc01);
            acc10 = fmaf(V.z, ftanh(A1.z + B0.z), acc10);
            acc11 = fmaf(V.z, ftanh(A1.z + B1.z), acc11);

            acc00 = fmaf(V.w, ftanh(A0.w + B0.w), acc00);
            acc01 = fmaf(V.w, ftanh(A0.w + B1.w), acc01);
            acc10 = fmaf(V.w, ftanh(A1.w + B0.w), acc10);
            acc11 = fmaf(V.w, ftanh(A1.w + B1.w), acc11);
        }
        __syncthreads();
    }

    const size_t base = ((size_t)b * TP_ + p0) * TQ_ + q0;
    g_sc[base + (size_t)ty * TQ_ + tx] = acc00;
    g_sc[base + (size_t)ty * TQ_ + tx + 16] = acc01;
    g_sc[base + (size_t)(ty + 16) * TQ_ + tx] = acc10;
    g_sc[base + (size_t)(ty + 16) * TQ_ + tx + 16] = acc11;
}

// ---------------------------------------------------------------------------
// Kernel 3: softmax over the p axis (axis=1 of [B,Tp,Tq]) -- column softmax.
// One thread per (b, q) column; accesses coalesced across threads.
// ---------------------------------------------------------------------------
__global__ __launch_bounds__(256) void softmax_kernel() {
    const int b = blockIdx.y;
    const int q = blockIdx.x * blockDim.x + threadIdx.x;
    float* s = g_sc + (size_t)b * TP_ * TQ_ + q;

    float m = -1e30f;
#pragma unroll 8
    for (int p = 0; p < TP_; p++) m = fmaxf(m, s[(size_t)p * TQ_]);

    float sum = 0.f;
#pragma unroll 8
    for (int p = 0; p < TP_; p++) {
        float e = __expf(s[(size_t)p * TQ_] - m);
        s[(size_t)p * TQ_] = e;
        sum += e;
    }

    float inv = __fdividef(1.0f, sum);
#pragma unroll 8
    for (int p = 0; p < TP_; p++) s[(size_t)p * TQ_] *= inv;
}

// ---------------------------------------------------------------------------
// Kernel 4: out[b,p,d] = sum_q weights[b,p,q] * q[b,q,d]
// Batched SGEMM: per-b  [Tp,Tq] x [Tq,D]
// 64x32 tiles (BK=32) -> 256 blocks (was 128).
// ---------------------------------------------------------------------------
__global__ __launch_bounds__(256) void out_gemm_kernel(const float* __restrict__ qin,
                                                       float* __restrict__ out) {
    const int b = blockIdx.z;
    gemm_tile<64, 32, 32, 4, 2>(g_sc + (size_t)b * TP_ * TQ_,
                                qin + (size_t)b * TQ_ * D_,
                                out + (size_t)b * TP_ * D_, TP_, D_, TQ_);
}

// ---------------------------------------------------------------------------
// Launch
// ---------------------------------------------------------------------------
extern "C" void kernel_launch(void* const* d_in, const int* in_sizes, int n_in,
                              void* d_out, int out_size) {
    const float* q = (const float*)d_in[0];   // [B,Tq,D]
    const float* p = (const float*)d_in[1];   // [B,Tp,D]
    const float* W0 = (const float*)d_in[2];  // [D,D]
    const float* W1 = (const float*)d_in[3];  // [D,D]
    const float* vc = (const float*)d_in[4];  // [D,1]
    float* out = (float*)d_out;               // [B,Tp,D]

    // 1. Projections: g_pq = q@W0, g_pp = p@W1  (one launch, z selects)
    {
        dim3 grid(D_ / 64, (B_ * TQ_) / 64, 2);
        proj_kernel<<<grid, 256>>>(q, p, W0, W1);
    }
    // 2. Energies + vc reduction
    {
        dim3 grid(TQ_ / 32, TP_ / 32, B_);
        energy_kernel<<<grid, 256>>>(vc);
    }
    // 3. Column softmax over p
    {
        dim3 grid(TQ_ / 256, B_);
        softmax_kernel<<<grid, 256>>>();
    }
    // 4. Output GEMM
    {
        dim3 grid(D_ / 32, TP_ / 64, B_);
        out_gemm_kernel<<<grid, 256>>>(q, out);
    }
}

// round 3
// speedup vs baseline: 1.8512x; 1.4636x over previous
#include <cuda_runtime.h>
#include <cuda_bf16.h>
#include <cstddef>

// Problem constants
#define B_   4
#define TQ_  512
#define TP_  512
#define D_   256

// ---------------------------------------------------------------------------
// Scratch (static device globals -- no dynamic allocation allowed)
// ---------------------------------------------------------------------------
__device__ float g_pq[(size_t)B_ * TQ_ * D_];    // q @ W0   [B,Tq,D]
__device__ float g_pp[(size_t)B_ * TP_ * D_];    // p @ W1   [B,Tp,D]
__device__ float g_sc[(size_t)B_ * TP_ * TQ_];   // scores / weights [B,Tp,Tq]
__device__ float g_part[2 * 1024 * 1024];        // 8MB split-K partials

// ---------------------------------------------------------------------------
// HW tanh: single MUFU.TANH (sm_75+).
// ---------------------------------------------------------------------------
__device__ __forceinline__ float ftanh(float x) {
    float r;
    asm("tanh.approx.f32 %0, %1;" : "=f"(r) : "f"(x));
    return r;
}

// ---------------------------------------------------------------------------
// Register-tiled SGEMM slice: C[M,N] += A[M, kbeg:kend] * B[kbeg:kend, N].
// Row-major fp32, 256 threads, register prefetch of the next K-tile so global
// latency overlaps compute. C is written (not accumulated) -- each split
// writes its own partial slice.
// ---------------------------------------------------------------------------
template <int BM, int BN, int BK, int TM, int TN>
__device__ __forceinline__ void gemm_tile(const float* __restrict__ A,
                                          const float* __restrict__ B,
                                          float* __restrict__ C,
                                          int N, int K, int kbeg, int kend,
                                          int m0, int n0) {
    constexpr int THREADS = (BM / TM) * (BN / TN);  // = 256
    __shared__ float As[BK][BM];  // transposed A tile
    __shared__ float Bs[BK][BN];

    const int tid = threadIdx.x;
    const int tnx = BN / TN;
    const int tx = tid % tnx;
    const int ty = tid / tnx;

    float acc[TM][TN];
#pragma unroll
    for (int i = 0; i < TM; i++)
#pragma unroll
        for (int j = 0; j < TN; j++) acc[i][j] = 0.0f;

    constexpr int A4 = BM * BK / (THREADS * 4);
    constexpr int B4 = BN * BK / (THREADS * 4);
    static_assert(A4 >= 1 && B4 >= 1, "tile too small for loader");

    float4 ra[A4], rb[B4];

    auto loadG = [&](int k0) {
#pragma unroll
        for (int s = 0; s < A4; s++) {
            int id = tid + s * THREADS;
            int r = id / (BK / 4);
            int c = (id % (BK / 4)) * 4;
            ra[s] = *(const float4*)&A[(size_t)(m0 + r) * K + k0 + c];
        }
#pragma unroll
        for (int s = 0; s < B4; s++) {
            int id = tid + s * THREADS;
            int r = id / (BN / 4);
            int c = (id % (BN / 4)) * 4;
            rb[s] = *(const float4*)&B[(size_t)(k0 + r) * N + n0 + c];
        }
    };
    auto storeS = [&]() {
#pragma unroll
        for (int s = 0; s < A4; s++) {
            int id = tid + s * THREADS;
            int r = id / (BK / 4);
            int c = (id % (BK / 4)) * 4;
            As[c + 0][r] = ra[s].x;
            As[c + 1][r] = ra[s].y;
            As[c + 2][r] = ra[s].z;
            As[c + 3][r] = ra[s].w;
        }
#pragma unroll
        for (int s = 0; s < B4; s++) {
            int id = tid + s * THREADS;
            int r = id / (BN / 4);
            int c = (id % (BN / 4)) * 4;
            *(float4*)&Bs[r][c] = rb[s];
        }
    };

    loadG(kbeg);
    for (int k0 = kbeg; k0 < kend; k0 += BK) {
        storeS();
        __syncthreads();
        if (k0 + BK < kend) loadG(k0 + BK);
#pragma unroll
        for (int k = 0; k < BK; k++) {
            float a[TM], bb[TN];
#pragma unroll
            for (int i = 0; i < TM; i += 4)
                *(float4*)&a[i] = *(const float4*)&As[k][ty * TM + i];
#pragma unroll
            for (int j = 0; j < TN; j += 4)
                *(float4*)&bb[j] = *(const float4*)&Bs[k][tx * TN + j];
#pragma unroll
            for (int i = 0; i < TM; i++)
#pragma unroll
                for (int j = 0; j < TN; j++)
                    acc[i][j] = fmaf(a[i], bb[j], acc[i][j]);
        }
        __syncthreads();
    }

#pragma unroll
    for (int i = 0; i < TM; i++)
#pragma unroll
        for (int j = 0; j < TN; j += 4) {
            float4 o = make_float4(acc[i][j], acc[i][j + 1], acc[i][j + 2],
                                   acc[i][j + 3]);
            *(float4*)&C[(size_t)(m0 + ty * TM + i) * N + n0 + tx * TN + j] = o;
        }
}

// ---------------------------------------------------------------------------
// Kernel 1: projections, split-K=2.  z encodes (split s, tensor t).
//   part[(s*2+t)] = (t?p:q)[:, ks:ks+128] @ (t?W1:W0)[ks:ks+128, :]
// grid (256/64, 2048/64, 4) = 512 blocks.
// ---------------------------------------------------------------------------
__global__ __launch_bounds__(256) void proj_kernel(const float* __restrict__ q,
                                                   const float* __restrict__ p,
                                                   const float* __restrict__ W0,
                                                   const float* __restrict__ W1) {
    const int t = blockIdx.z & 1;
    const int s = blockIdx.z >> 1;
    const float* A = t ? p : q;
    const float* Bw = t ? W1 : W0;
    float* C = g_part + (size_t)(s * 2 + t) * (B_ * TQ_ * D_);
    gemm_tile<64, 64, 32, 4, 4>(A, Bw, C, D_, D_, s * 128, s * 128 + 128,
                                blockIdx.y * 64, blockIdx.x * 64);
}

// Reduce proj partials: g_pq = part[0*2+0]+part[1*2+0]; g_pp likewise (t=1).
__global__ __launch_bounds__(256) void proj_reduce_kernel() {
    const int i = blockIdx.x * 256 + threadIdx.x;  // float4 index, [0, 262144)
    constexpr int NF4 = (B_ * TQ_ * D_) / 4;       // 131072 per tensor
    const int t = (i < NF4) ? 0 : 1;
    const int j = (t == 0) ? i : (i - NF4);
    const float4* p0 = (const float4*)g_part + (size_t)(0 * 2 + t) * NF4 + j;
    const float4* p1 = (const float4*)g_part + (size_t)(1 * 2 + t) * NF4 + j;
    float4 a = *p0, b = *p1;
    float4 r = make_float4(a.x + b.x, a.y + b.y, a.z + b.z, a.w + b.w);
    float4* dst = (float4*)(t ? g_pp : g_pq) + j;
    *dst = r;
}

// ---------------------------------------------------------------------------
// Kernel 2: energies + vc reduction (MUFU-bound).
// ---------------------------------------------------------------------------
__global__ __launch_bounds__(256) void energy_kernel(const float* __restrict__ vc) {
    __shared__ float sp[32][68];
    __shared__ float sq[32][68];
    __shared__ float sv[64];

    const int b = blockIdx.z;
    const int p0 = blockIdx.y * 32;
    const int q0 = blockIdx.x * 32;
    const int tid = threadIdx.x;
    const int tx = tid & 15;
    const int ty = tid >> 4;

    const float* ppb = g_pp + ((size_t)b * TP_ + p0) * D_;
    const float* pqb = g_pq + ((size_t)b * TQ_ + q0) * D_;

    float acc00 = 0.f, acc01 = 0.f, acc10 = 0.f, acc11 = 0.f;

    const int vr = tid >> 2;
    const int cb = (tid & 3) * 16;

    for (int d0 = 0; d0 < D_; d0 += 64) {
        if (tid < 64) sv[tid] = vc[d0 + tid];
        const float* src = (vr < 32) ? (ppb + (size_t)vr * D_ + d0)
                                     : (pqb + (size_t)(vr - 32) * D_ + d0);
        float* dst = (vr < 32) ? &sp[vr][0] : &sq[vr - 32][0];
#pragma unroll
        for (int j = 0; j < 16; j += 4)
            *(float4*)&dst[cb + j] = *(const float4*)&src[cb + j];
        __syncthreads();

#pragma unroll 2
        for (int d = 0; d < 64; d += 4) {
            float4 A0 = *(float4*)&sp[ty][d];
            float4 A1 = *(float4*)&sp[ty + 16][d];
            float4 B0 = *(float4*)&sq[tx][d];
            float4 B1 = *(float4*)&sq[tx + 16][d];
            float4 V = *(float4*)&sv[d];

            acc00 = fmaf(V.x, ftanh(A0.x + B0.x), acc00);
            acc01 = fmaf(V.x, ftanh(A0.x + B1.x), acc01);
            acc10 = fmaf(V.x, ftanh(A1.x + B0.x), acc10);
            acc11 = fmaf(V.x, ftanh(A1.x + B1.x), acc11);

            acc00 = fmaf(V.y, ftanh(A0.y + B0.y), acc00);
            acc01 = fmaf(V.y, ftanh(A0.y + B1.y), acc01);
            acc10 = fmaf(V.y, ftanh(A1.y + B0.y), acc10);
            acc11 = fmaf(V.y, ftanh(A1.y + B1.y), acc11);

            acc00 = fmaf(V.z, ftanh(A0.z + B0.z), acc00);
            acc01 = fmaf(V.z, ftanh(A0.z + B1.z), acc01);
            acc10 = fmaf(V.z, ftanh(A1.z + B0.z), acc10);
            acc11 = fmaf(V.z, ftanh(A1.z + B1.z), acc11);

            acc00 = fmaf(V.w, ftanh(A0.w + B0.w), acc00);
            acc01 = fmaf(V.w, ftanh(A0.w + B1.w), acc01);
            acc10 = fmaf(V.w, ftanh(A1.w + B0.w), acc10);
            acc11 = fmaf(V.w, ftanh(A1.w + B1.w), acc11);
        }
        __syncthreads();
    }

    const size_t base = ((size_t)b * TP_ + p0) * TQ_ + q0;
    g_sc[base + (size_t)ty * TQ_ + tx] = acc00;
    g_sc[base + (size_t)ty * TQ_ + tx + 16] = acc01;
    g_sc[base + (size_t)(ty + 16) * TQ_ + tx] = acc10;
    g_sc[base + (size_t)(ty + 16) * TQ_ + tx + 16] = acc11;
}

// ---------------------------------------------------------------------------
// Kernel 3: softmax over the p axis (column softmax).
// Block: 32 q-lanes x 8 p-strips (256 thr). Grid: (TQ/32, B) = 64 blocks.
// Coalesced 128B row segments, smem reduction across the 8 strips.
// ---------------------------------------------------------------------------
__global__ __launch_bounds__(256) void softmax_kernel() {
    __shared__ float red[8][33];

    const int b = blockIdx.y;
    const int tx = threadIdx.x & 31;         // q within chunk
    const int ty = threadIdx.x >> 5;         // p strip 0..7
    const int q = blockIdx.x * 32 + tx;
    float* s = g_sc + (size_t)b * TP_ * TQ_ + q;

    // pass 1: max over p
    float m = -1e30f;
#pragma unroll 8
    for (int p = ty; p < TP_; p += 8) m = fmaxf(m, s[(size_t)p * TQ_]);
    red[ty][tx] = m;
    __syncthreads();
    if (ty == 0) {
        float mm = red[0][tx];
#pragma unroll
        for (int k = 1; k < 8; k++) mm = fmaxf(mm, red[k][tx]);
        red[0][tx] = mm;
    }
    __syncthreads();
    m = red[0][tx];
    __syncthreads();

    // pass 2: exp + sum
    float sum = 0.f;
#pragma unroll 8
    for (int p = ty; p < TP_; p += 8) {
        float e = __expf(s[(size_t)p * TQ_] - m);
        s[(size_t)p * TQ_] = e;
        sum += e;
    }
    red[ty][tx] = sum;
    __syncthreads();
    if (ty == 0) {
        float ss = red[0][tx];
#pragma unroll
        for (int k = 1; k < 8; k++) ss += red[k][tx];
        red[0][tx] = __fdividef(1.0f, ss);
    }
    __syncthreads();
    const float inv = red[0][tx];

    // pass 3: normalize
#pragma unroll 8
    for (int p = ty; p < TP_; p += 8) s[(size_t)p * TQ_] *= inv;
}

// ---------------------------------------------------------------------------
// Kernel 4: out GEMM, split-K=4.  z encodes (split s, batch b).
//   part[(s*4+b)] = weights[b][:, ks:ks+128] @ q[b][ks:ks+128, :]
// grid (256/64, 512/64, 16) = 512 blocks.
// ---------------------------------------------------------------------------
__global__ __launch_bounds__(256) void out_gemm_kernel(const float* __restrict__ qin) {
    const int b = blockIdx.z & 3;
    const int s = blockIdx.z >> 2;
    float* C = g_part + (size_t)(s * 4 + b) * (TP_ * D_);
    gemm_tile<64, 64, 32, 4, 4>(g_sc + (size_t)b * TP_ * TQ_,
                                qin + (size_t)b * TQ_ * D_, C, D_, TQ_,
                                s * 128, s * 128 + 128,
                                blockIdx.y * 64, blockIdx.x * 64);
}

// Reduce out partials: out = sum over 4 splits.
__global__ __launch_bounds__(256) void out_reduce_kernel(float* __restrict__ out) {
    const int i = blockIdx.x * 256 + threadIdx.x;  // float4 idx, [0, 131072)
    constexpr int NB4 = (TP_ * D_) / 4;            // 32768 per batch
    const int b = i / NB4;
    const int j = i % NB4;
    float4 r = make_float4(0.f, 0.f, 0.f, 0.f);
#pragma unroll
    for (int s = 0; s < 4; s++) {
        float4 v = *((const float4*)g_part + (size_t)(s * 4 + b) * NB4 + j);
        r.x += v.x; r.y += v.y; r.z += v.z; r.w += v.w;
    }
    *((float4*)out + i) = r;
}

// ---------------------------------------------------------------------------
// Launch
// ---------------------------------------------------------------------------
extern "C" void kernel_launch(void* const* d_in, const int* in_sizes, int n_in,
                              void* d_out, int out_size) {
    const float* q = (const float*)d_in[0];   // [B,Tq,D]
    const float* p = (const float*)d_in[1];   // [B,Tp,D]
    const float* W0 = (const float*)d_in[2];  // [D,D]
    const float* W1 = (const float*)d_in[3];  // [D,D]
    const float* vc = (const float*)d_in[4];  // [D,1]
    float* out = (float*)d_out;               // [B,Tp,D]

    // 1. Projections (split-K=2) + reduce
    {
        dim3 grid(D_ / 64, (B_ * TQ_) / 64, 4);
        proj_kernel<<<grid, 256>>>(q, p, W0, W1);
        proj_reduce_kernel<<<(2 * B_ * TQ_ * D_ / 4) / 256, 256>>>();
    }
    // 2. Energies + vc reduction
    {
        dim3 grid(TQ_ / 32, TP_ / 32, B_);
        energy_kernel<<<grid, 256>>>(vc);
    }
    // 3. Column softmax over p
    {
        dim3 grid(TQ_ / 32, B_);
        softmax_kernel<<<grid, 256>>>();
    }
    // 4. Output GEMM (split-K=4) + reduce
    {
        dim3 grid(D_ / 64, TP_ / 64, 16);
        out_gemm_kernel<<<grid, 256>>>(q);
        out_reduce_kernel<<<(B_ * TP_ * D_ / 4) / 256, 256>>>(out);
    }
}

// round 4
// speedup vs baseline: 1.8522x; 1.0005x over previous
#include <cuda_runtime.h>
#include <cuda_fp16.h>
#include <cuda_bf16.h>
#include <cstddef>
#include <cstdint>

// Problem constants
#define B_   4
#define TQ_  512
#define TP_  512
#define D_   256

// ---------------------------------------------------------------------------
// Scratch (static device globals -- no dynamic allocation allowed)
// ---------------------------------------------------------------------------
__device__ __align__(16) __half g_pqh[(size_t)B_ * TQ_ * D_];  // fp16 q@W0
__device__ __align__(16) __half g_pph[(size_t)B_ * TP_ * D_];  // fp16 p@W1
__device__ float g_sc[(size_t)B_ * TP_ * TQ_];   // exp(scores) [B,Tp,Tq]
__device__ float g_inv[B_ * TQ_];                // 1 / sum_p exp(score)
__device__ float g_part[2 * 1024 * 1024];        // 8MB split-K partials

// ---------------------------------------------------------------------------
// HW tanh on packed fp16x2: one MUFU slot per TWO elements.
// ---------------------------------------------------------------------------
__device__ __forceinline__ __half2 htanh2(__half2 x) {
    uint32_t xi = *reinterpret_cast<uint32_t*>(&x), ri;
    asm("tanh.approx.f16x2 %0, %1;" : "=r"(ri) : "r"(xi));
    return *reinterpret_cast<__half2*>(&ri);
}

// ---------------------------------------------------------------------------
// Register-tiled SGEMM slice with register prefetch.
// C[M,N] (partial) = A[M, kbeg:kend] * B[kbeg:kend, N], row-major fp32.
// If SCALE, A columns are scaled by colscale[k] while loading to smem.
// ---------------------------------------------------------------------------
template <int BM, int BN, int BK, int TM, int TN, bool SCALE>
__device__ __forceinline__ void gemm_tile(const float* __restrict__ A,
                                          const float* __restrict__ B,
                                          float* __restrict__ C,
                                          const float* __restrict__ colscale,
                                          int N, int K, int kbeg, int kend,
                                          int m0, int n0) {
    constexpr int THREADS = (BM / TM) * (BN / TN);  // = 256
    __shared__ float As[BK][BM];
    __shared__ float Bs[BK][BN];

    const int tid = threadIdx.x;
    const int tnx = BN / TN;
    const int tx = tid % tnx;
    const int ty = tid / tnx;

    float acc[TM][TN];
#pragma unroll
    for (int i = 0; i < TM; i++)
#pragma unroll
        for (int j = 0; j < TN; j++) acc[i][j] = 0.0f;

    constexpr int A4 = BM * BK / (THREADS * 4);
    constexpr int B4 = BN * BK / (THREADS * 4);
    static_assert(A4 >= 1 && B4 >= 1, "tile too small for loader");

    float4 ra[A4], rb[B4];

    auto loadG = [&](int k0) {
#pragma unroll
        for (int s = 0; s < A4; s++) {
            int id = tid + s * THREADS;
            int r = id / (BK / 4);
            int c = (id % (BK / 4)) * 4;
            ra[s] = *(const float4*)&A[(size_t)(m0 + r) * K + k0 + c];
            if (SCALE) {
                float4 sc = *(const float4*)&colscale[k0 + c];
                ra[s].x *= sc.x; ra[s].y *= sc.y;
                ra[s].z *= sc.z; ra[s].w *= sc.w;
            }
        }
#pragma unroll
        for (int s = 0; s < B4; s++) {
            int id = tid + s * THREADS;
            int r = id / (BN / 4);
            int c = (id % (BN / 4)) * 4;
            rb[s] = *(const float4*)&B[(size_t)(k0 + r) * N + n0 + c];
        }
    };
    auto storeS = [&]() {
#pragma unroll
        for (int s = 0; s < A4; s++) {
            int id = tid + s * THREADS;
            int r = id / (BK / 4);
            int c = (id % (BK / 4)) * 4;
            As[c + 0][r] = ra[s].x;
            As[c + 1][r] = ra[s].y;
            As[c + 2][r] = ra[s].z;
            As[c + 3][r] = ra[s].w;
        }
#pragma unroll
        for (int s = 0; s < B4; s++) {
            int id = tid + s * THREADS;
            int r = id / (BN / 4);
            int c = (id % (BN / 4)) * 4;
            *(float4*)&Bs[r][c] = rb[s];
        }
    };

    loadG(kbeg);
    for (int k0 = kbeg; k0 < kend; k0 += BK) {
        storeS();
        __syncthreads();
        if (k0 + BK < kend) loadG(k0 + BK);
#pragma unroll
        for (int k = 0; k < BK; k++) {
            float a[TM], bb[TN];
#pragma unroll
            for (int i = 0; i < TM; i += 4)
                *(float4*)&a[i] = *(const float4*)&As[k][ty * TM + i];
#pragma unroll
            for (int j = 0; j < TN; j += 4)
                *(float4*)&bb[j] = *(const float4*)&Bs[k][tx * TN + j];
#pragma unroll
            for (int i = 0; i < TM; i++)
#pragma unroll
                for (int j = 0; j < TN; j++)
                    acc[i][j] = fmaf(a[i], bb[j], acc[i][j]);
        }
        __syncthreads();
    }

#pragma unroll
    for (int i = 0; i < TM; i++)
#pragma unroll
        for (int j = 0; j < TN; j += 4) {
            float4 o = make_float4(acc[i][j], acc[i][j + 1], acc[i][j + 2],
                                   acc[i][j + 3]);
            *(float4*)&C[(size_t)(m0 + ty * TM + i) * N + n0 + tx * TN + j] = o;
        }
}

// ---------------------------------------------------------------------------
// Kernel 1: projections, split-K=2.  z encodes (split s, tensor t).
// ---------------------------------------------------------------------------
__global__ __launch_bounds__(256) void proj_kernel(const float* __restrict__ q,
                                                   const float* __restrict__ p,
                                                   const float* __restrict__ W0,
                                                   const float* __restrict__ W1) {
    const int t = blockIdx.z & 1;
    const int s = blockIdx.z >> 1;
    const float* A = t ? p : q;
    const float* Bw = t ? W1 : W0;
    float* C = g_part + (size_t)(s * 2 + t) * (B_ * TQ_ * D_);
    gemm_tile<64, 64, 32, 4, 4, false>(A, Bw, C, nullptr, D_, D_,
                                       s * 128, s * 128 + 128,
                                       blockIdx.y * 64, blockIdx.x * 64);
}

// Reduce proj partials and convert to fp16: g_pqh (t=0), g_pph (t=1).
__global__ __launch_bounds__(256) void proj_reduce_kernel() {
    const int i = blockIdx.x * 256 + threadIdx.x;  // float4 index
    constexpr int NF4 = (B_ * TQ_ * D_) / 4;       // 131072 per tensor
    const int t = (i < NF4) ? 0 : 1;
    const int j = (t == 0) ? i : (i - NF4);
    const float4* p0 = (const float4*)g_part + (size_t)(0 * 2 + t) * NF4 + j;
    const float4* p1 = (const float4*)g_part + (size_t)(1 * 2 + t) * NF4 + j;
    float4 a = *p0, b = *p1;
    __half2 h0 = __floats2half2_rn(a.x + b.x, a.y + b.y);
    __half2 h1 = __floats2half2_rn(a.z + b.z, a.w + b.w);
    uint2 u;
    u.x = *reinterpret_cast<uint32_t*>(&h0);
    u.y = *reinterpret_cast<uint32_t*>(&h1);
    uint2* dst = (uint2*)(t ? g_pph : g_pqh) + j;
    *dst = u;
}

// ---------------------------------------------------------------------------
// Kernel 2: energies -> exp(score).  fp16x2 hybrid path.
//   e[b,p,q] = exp( sum_d vc[d] * tanh(pp[b,p,d] + pq[b,q,d]) )
// 64x64 tile per block (256 thr, 4x4 micro-tile), d chunked by 64.
// Two d-values packed per half2 lane; fp16 accs spilled to fp32 every 32 d.
// No max subtraction: |score| <= sum|vc| ~ 10, exp safe in fp32.
// ---------------------------------------------------------------------------
__global__ __launch_bounds__(256) void energy_kernel(const float* __restrict__ vc) {
    __shared__ __half2 sp2[64][33];
    __shared__ __half2 sq2[64][33];
    __shared__ __half2 sv2[32];

    const int b = blockIdx.z;
    const int p0 = blockIdx.y * 64;
    const int q0 = blockIdx.x * 64;
    const int tid = threadIdx.x;
    const int tx = tid & 15;
    const int ty = tid >> 4;

    const uint4* ppb = (const uint4*)g_pph + ((size_t)b * TP_ + p0) * (D_ / 8);
    const uint4* pqb = (const uint4*)g_pqh + ((size_t)b * TQ_ + q0) * (D_ / 8);

    float accf[4][4];
#pragma unroll
    for (int i = 0; i < 4; i++)
#pragma unroll
        for (int j = 0; j < 4; j++) accf[i][j] = 0.0f;

    for (int d0 = 0; d0 < D_; d0 += 64) {
        // load vc pairs for this chunk
        if (tid < 32) {
            float2 v = *(const float2*)&vc[d0 + tid * 2];
            sv2[tid] = __floats2half2_rn(v.x, v.y);
        }
        // load 64 rows x 8 uint4 per array (2 per thread per array)
#pragma unroll
        for (int s = 0; s < 2; s++) {
            int id = tid + s * 256;
            int row = id >> 3;
            int c8 = id & 7;
            uint4 vP = ppb[(size_t)row * (D_ / 8) + (d0 >> 3) + c8];
            uint4 vQ = pqb[(size_t)row * (D_ / 8) + (d0 >> 3) + c8];
            uint32_t* dp = (uint32_t*)&sp2[row][c8 * 4];
            uint32_t* dq = (uint32_t*)&sq2[row][c8 * 4];
            dp[0] = vP.x; dp[1] = vP.y; dp[2] = vP.z; dp[3] = vP.w;
            dq[0] = vQ.x; dq[1] = vQ.y; dq[2] = vQ.z; dq[3] = vQ.w;
        }
        __syncthreads();

        // two 32-d half-chunks; spill fp16 accs to fp32 after each
#pragma unroll
        for (int h = 0; h < 2; h++) {
            __half2 acc2[4][4];
#pragma unroll
            for (int i = 0; i < 4; i++)
#pragma unroll
                for (int j = 0; j < 4; j++)
                    acc2[i][j] = __floats2half2_rn(0.f, 0.f);

#pragma unroll
            for (int d2 = h * 16; d2 < h * 16 + 16; d2++) {
                __half2 v = sv2[d2];
                __half2 a[4], bq[4];
#pragma unroll
                for (int i = 0; i < 4; i++) a[i] = sp2[ty * 4 + i][d2];
#pragma unroll
                for (int j = 0; j < 4; j++) bq[j] = sq2[tx * 4 + j][d2];
#pragma unroll
                for (int i = 0; i < 4; i++)
#pragma unroll
                    for (int j = 0; j < 4; j++) {
                        __half2 t = htanh2(__hadd2(a[i], bq[j]));
                        acc2[i][j] = __hfma2(v, t, acc2[i][j]);
                    }
            }
#pragma unroll
            for (int i = 0; i < 4; i++)
#pragma unroll
                for (int j = 0; j < 4; j++) {
                    float2 f = __half22float2(acc2[i][j]);
                    accf[i][j] += f.x + f.y;
                }
        }
        __syncthreads();
    }

    // write exp(score)
#pragma unroll
    for (int i = 0; i < 4; i++) {
        float4 o;
        o.x = __expf(accf[i][0]);
        o.y = __expf(accf[i][1]);
        o.z = __expf(accf[i][2]);
        o.w = __expf(accf[i][3]);
        *(float4*)&g_sc[((size_t)b * TP_ + p0 + ty * 4 + i) * TQ_ + q0 + tx * 4] = o;
    }
}

// ---------------------------------------------------------------------------
// Kernel 3: column sums of e over p -> g_inv = 1/sum.  Deterministic.
// Block: 16 q-lanes x 32 p-strips (512 thr). Grid: (TQ/16, B) = 128 blocks.
// ---------------------------------------------------------------------------
__global__ __launch_bounds__(512) void colsum_kernel() {
    __shared__ float red[32][17];

    const int b = blockIdx.y;
    const int tx = threadIdx.x & 15;
    const int ty = threadIdx.x >> 4;
    const int q = blockIdx.x * 16 + tx;
    const float* s = g_sc + (size_t)b * TP_ * TQ_ + q;

    float sum = 0.f;
#pragma unroll 8
    for (int p = ty; p < TP_; p += 32) sum += s[(size_t)p * TQ_];
    red[ty][tx] = sum;
    __syncthreads();
    if (ty == 0) {
        float ss = red[0][tx];
#pragma unroll
        for (int k = 1; k < 32; k++) ss += red[k][tx];
        g_inv[b * TQ_ + q] = __fdividef(1.0f, ss);
    }
}

// ---------------------------------------------------------------------------
// Kernel 4: out GEMM, split-K=4, A-tile scaled by g_inv[q] at load.
//   part[(s*4+b)] = (e .* inv)[b][:, ks:ks+128] @ q[b][ks:ks+128, :]
// ---------------------------------------------------------------------------
__global__ __launch_bounds__(256) void out_gemm_kernel(const float* __restrict__ qin) {
    const int b = blockIdx.z & 3;
    const int s = blockIdx.z >> 2;
    float* C = g_part + (size_t)(s * 4 + b) * (TP_ * D_);
    gemm_tile<64, 64, 32, 4, 4, true>(g_sc + (size_t)b * TP_ * TQ_,
                                      qin + (size_t)b * TQ_ * D_, C,
                                      g_inv + b * TQ_, D_, TQ_,
                                      s * 128, s * 128 + 128,
                                      blockIdx.y * 64, blockIdx.x * 64);
}

// Reduce out partials: out = sum over 4 splits.
__global__ __launch_bounds__(256) void out_reduce_kernel(float* __restrict__ out) {
    const int i = blockIdx.x * 256 + threadIdx.x;
    constexpr int NB4 = (TP_ * D_) / 4;
    const int b = i / NB4;
    const int j = i % NB4;
    float4 r = make_float4(0.f, 0.f, 0.f, 0.f);
#pragma unroll
    for (int s = 0; s < 4; s++) {
        float4 v = *((const float4*)g_part + (size_t)(s * 4 + b) * NB4 + j);
        r.x += v.x; r.y += v.y; r.z += v.z; r.w += v.w;
    }
    *((float4*)out + i) = r;
}

// ---------------------------------------------------------------------------
// Launch
// ---------------------------------------------------------------------------
extern "C" void kernel_launch(void* const* d_in, const int* in_sizes, int n_in,
                              void* d_out, int out_size) {
    const float* q = (const float*)d_in[0];   // [B,Tq,D]
    const float* p = (const float*)d_in[1];   // [B,Tp,D]
    const float* W0 = (const float*)d_in[2];  // [D,D]
    const float* W1 = (const float*)d_in[3];  // [D,D]
    const float* vc = (const float*)d_in[4];  // [D,1]
    float* out = (float*)d_out;               // [B,Tp,D]

    // 1. Projections (split-K=2) + reduce->fp16
    {
        dim3 grid(D_ / 64, (B_ * TQ_) / 64, 4);
        proj_kernel<<<grid, 256>>>(q, p, W0, W1);
        proj_reduce_kernel<<<(2 * B_ * TQ_ * D_ / 4) / 256, 256>>>();
    }
    // 2. Energies -> exp(score)
    {
        dim3 grid(TQ_ / 64, TP_ / 64, B_);
        energy_kernel<<<grid, 256>>>(vc);
    }
    // 3. Column sums -> inverse
    {
        dim3 grid(TQ_ / 16, B_);
        colsum_kernel<<<grid, 512>>>();
    }
    // 4. Output GEMM (split-K=4, fused normalize) + reduce
    {
        dim3 grid(D_ / 64, TP_ / 64, 16);
        out_gemm_kernel<<<grid, 256>>>(q);
        out_reduce_kernel<<<(B_ * TP_ * D_ / 4) / 256, 256>>>(out);
    }
}

// round 5
// speedup vs baseline: 2.2738x; 1.2276x over previous
#include <cuda_runtime.h>
#include <cuda_fp16.h>
#include <cuda_bf16.h>
#include <cstddef>
#include <cstdint>

// Problem constants
#define B_   4
#define TQ_  512
#define TP_  512
#define D_   256

// ---------------------------------------------------------------------------
// Scratch (static device globals)
// ---------------------------------------------------------------------------
__device__ float g_pq[(size_t)B_ * TQ_ * D_];   // q @ W0  [B,Tq,D]
__device__ float g_pp[(size_t)B_ * TP_ * D_];   // p @ W1  [B,Tp,D]
__device__ float g_sc[(size_t)B_ * TP_ * TQ_];  // exp(scores) [B,Tp,Tq]
__device__ float g_inv[B_ * TQ_];               // 1 / sum_p exp(score)

// ---------------------------------------------------------------------------
// fp32 HW tanh (1 MUFU op) -- f16x2 variant measured at half rate, no gain.
// ---------------------------------------------------------------------------
__device__ __forceinline__ float ftanh(float x) {
    float r;
    asm("tanh.approx.f32 %0, %1;" : "=f"(r) : "f"(x));
    return r;
}

__device__ __forceinline__ uint32_t f2tf32(float x) {
    uint32_t r;
    asm("cvt.rna.tf32.f32 %0, %1;" : "=r"(r) : "f"(x));
    return r;
}

// ---------------------------------------------------------------------------
// tf32 tensor-core GEMM, 64x64 block tile, 256 threads (8 warps 2x4),
// warp tile 32x16 (2 m-frags x 2 n-frags of m16n8k8).
// C[M,N] = A[M,K] (row) * B[K,N] (row).  If SCALE, A col k scaled by cs[k].
// ---------------------------------------------------------------------------
template <bool SCALE>
__device__ __forceinline__ void tf32_gemm_64x64(const float* __restrict__ A,
                                                const float* __restrict__ B,
                                                float* __restrict__ C,
                                                const float* __restrict__ cs,
                                                int N, int K, int m0, int n0) {
    __shared__ uint32_t As[64][36];  // [m][k] pad->36: conflict-free frags
    __shared__ uint32_t Bs[32][72];  // [k][n] pad->72: conflict-free frags

    const int tid = threadIdx.x;
    const int lane = tid & 31;
    const int w = tid >> 5;
    const int wm = (w >> 2) * 32;   // warp m offset: 0/32
    const int wn = (w & 3) * 16;    // warp n offset: 0..48
    const int frow = lane >> 2;     // fragment row 0..7
    const int fcol = lane & 3;      // fragment col 0..3

    float c[2][2][4];
#pragma unroll
    for (int mi = 0; mi < 2; mi++)
#pragma unroll
        for (int ni = 0; ni < 2; ni++)
#pragma unroll
            for (int k = 0; k < 4; k++) c[mi][ni][k] = 0.0f;

    float4 ra[2], rb[2];
    auto loadG = [&](int k0) {
#pragma unroll
        for (int s = 0; s < 2; s++) {
            int id = tid + s * 256;
            int r = id >> 3, cc = (id & 7) * 4;
            ra[s] = *(const float4*)&A[(size_t)(m0 + r) * K + k0 + cc];
            if (SCALE) {
                float4 sc = *(const float4*)&cs[k0 + cc];
                ra[s].x *= sc.x; ra[s].y *= sc.y;
                ra[s].z *= sc.z; ra[s].w *= sc.w;
            }
        }
#pragma unroll
        for (int s = 0; s < 2; s++) {
            int id = tid + s * 256;
            int r = id >> 4, cc = (id & 15) * 4;
            rb[s] = *(const float4*)&B[(size_t)(k0 + r) * N + n0 + cc];
        }
    };
    auto storeS = [&]() {
#pragma unroll
        for (int s = 0; s < 2; s++) {
            int id = tid + s * 256;
            int r = id >> 3, cc = (id & 7) * 4;
            As[r][cc + 0] = f2tf32(ra[s].x);
            As[r][cc + 1] = f2tf32(ra[s].y);
            As[r][cc + 2] = f2tf32(ra[s].z);
            As[r][cc + 3] = f2tf32(ra[s].w);
        }
#pragma unroll
        for (int s = 0; s < 2; s++) {
            int id = tid + s * 256;
            int r = id >> 4, cc = (id & 15) * 4;
            Bs[r][cc + 0] = f2tf32(rb[s].x);
            Bs[r][cc + 1] = f2tf32(rb[s].y);
            Bs[r][cc + 2] = f2tf32(rb[s].z);
            Bs[r][cc + 3] = f2tf32(rb[s].w);
        }
    };

    loadG(0);
    for (int k0 = 0; k0 < K; k0 += 32) {
        storeS();
        __syncthreads();
        if (k0 + 32 < K) loadG(k0 + 32);
#pragma unroll
        for (int ks = 0; ks < 4; ks++) {
            const int kk = ks * 8;
            uint32_t a[2][4], bfr[2][2];
#pragma unroll
            for (int mi = 0; mi < 2; mi++) {
                a[mi][0] = As[wm + mi * 16 + frow][kk + fcol];
                a[mi][1] = As[wm + mi * 16 + frow + 8][kk + fcol];
                a[mi][2] = As[wm + mi * 16 + frow][kk + fcol + 4];
                a[mi][3] = As[wm + mi * 16 + frow + 8][kk + fcol + 4];
            }
#pragma unroll
            for (int ni = 0; ni < 2; ni++) {
                bfr[ni][0] = Bs[kk + fcol][wn + ni * 8 + frow];
                bfr[ni][1] = Bs[kk + fcol + 4][wn + ni * 8 + frow];
            }
#pragma unroll
            for (int mi = 0; mi < 2; mi++)
#pragma unroll
                for (int ni = 0; ni < 2; ni++)
                    asm volatile(
                        "mma.sync.aligned.m16n8k8.row.col.f32.tf32.tf32.f32 "
                        "{%0,%1,%2,%3},{%4,%5,%6,%7},{%8,%9},{%0,%1,%2,%3};"
                        : "+f"(c[mi][ni][0]), "+f"(c[mi][ni][1]),
                          "+f"(c[mi][ni][2]), "+f"(c[mi][ni][3])
                        : "r"(a[mi][0]), "r"(a[mi][1]), "r"(a[mi][2]),
                          "r"(a[mi][3]), "r"(bfr[ni][0]), "r"(bfr[ni][1]));
        }
        __syncthreads();
    }

    // Epilogue: c0,c1 -> (row, 2j..2j+1), c2,c3 -> (row+8, ...)
#pragma unroll
    for (int mi = 0; mi < 2; mi++)
#pragma unroll
        for (int ni = 0; ni < 2; ni++) {
            int rr = m0 + wm + mi * 16 + frow;
            int cc = n0 + wn + ni * 8 + fcol * 2;
            *(float2*)&C[(size_t)rr * N + cc] =
                make_float2(c[mi][ni][0], c[mi][ni][1]);
            *(float2*)&C[(size_t)(rr + 8) * N + cc] =
                make_float2(c[mi][ni][2], c[mi][ni][3]);
        }
}

// ---------------------------------------------------------------------------
// Kernel 1: projections (tf32 TC).  z: 0 -> g_pq = q@W0, 1 -> g_pp = p@W1.
// grid (256/64, 2048/64, 2) = 256 blocks.
// ---------------------------------------------------------------------------
__global__ __launch_bounds__(256) void proj_kernel(const float* __restrict__ q,
                                                   const float* __restrict__ p,
                                                   const float* __restrict__ W0,
                                                   const float* __restrict__ W1) {
    const int t = blockIdx.z;
    const float* A = t ? p : q;
    const float* Bw = t ? W1 : W0;
    float* C = t ? g_pp : g_pq;
    tf32_gemm_64x64<false>(A, Bw, C, nullptr, D_, D_,
                           blockIdx.y * 64, blockIdx.x * 64);
}

// ---------------------------------------------------------------------------
// Kernel 2: energies -> exp(score).  fp32 MUFU.TANH, 64x64 tile, 4x4 micro.
//   e[b,p,q] = exp( sum_d vc[d] * tanh(pp[b,p,d] + pq[b,q,d]) )
// No max subtraction: |score| <= sum|vc| ~ 10, exp safe in fp32.
// ---------------------------------------------------------------------------
__global__ __launch_bounds__(256) void energy_kernel(const float* __restrict__ vc) {
    __shared__ float sp[64][33];  // odd stride: 2-way worst case on b-loads
    __shared__ float sq[64][33];
    __shared__ float sv[32];

    const int b = blockIdx.z;
    const int p0 = blockIdx.y * 64;
    const int q0 = blockIdx.x * 64;
    const int tid = threadIdx.x;
    const int tx = tid & 15;
    const int ty = tid >> 4;

    const float* ppb = g_pp + ((size_t)b * TP_ + p0) * D_;
    const float* pqb = g_pq + ((size_t)b * TQ_ + q0) * D_;

    float acc[4][4];
#pragma unroll
    for (int i = 0; i < 4; i++)
#pragma unroll
        for (int j = 0; j < 4; j++) acc[i][j] = 0.0f;

    for (int d0 = 0; d0 < D_; d0 += 32) {
        if (tid < 32) sv[tid] = vc[d0 + tid];
#pragma unroll
        for (int s = 0; s < 2; s++) {
            int id = tid + s * 256;
            int r = id >> 3, cc = (id & 7) * 4;
            float4 vP = *(const float4*)&ppb[(size_t)r * D_ + d0 + cc];
            float4 vQ = *(const float4*)&pqb[(size_t)r * D_ + d0 + cc];
            sp[r][cc + 0] = vP.x; sp[r][cc + 1] = vP.y;
            sp[r][cc + 2] = vP.z; sp[r][cc + 3] = vP.w;
            sq[r][cc + 0] = vQ.x; sq[r][cc + 1] = vQ.y;
            sq[r][cc + 2] = vQ.z; sq[r][cc + 3] = vQ.w;
        }
        __syncthreads();

#pragma unroll 8
        for (int d = 0; d < 32; d++) {
            float v = sv[d];
            float a[4], bb[4];
#pragma unroll
            for (int i = 0; i < 4; i++) a[i] = sp[ty * 4 + i][d];
#pragma unroll
            for (int j = 0; j < 4; j++) bb[j] = sq[tx * 4 + j][d];
#pragma unroll
            for (int i = 0; i < 4; i++)
#pragma unroll
                for (int j = 0; j < 4; j++)
                    acc[i][j] = fmaf(v, ftanh(a[i] + bb[j]), acc[i][j]);
        }
        __syncthreads();
    }

#pragma unroll
    for (int i = 0; i < 4; i++) {
        float4 o;
        o.x = __expf(acc[i][0]);
        o.y = __expf(acc[i][1]);
        o.z = __expf(acc[i][2]);
        o.w = __expf(acc[i][3]);
        *(float4*)&g_sc[((size_t)b * TP_ + p0 + ty * 4 + i) * TQ_ + q0 + tx * 4] = o;
    }
}

// ---------------------------------------------------------------------------
// Kernel 3: column sums of e over p -> g_inv = 1/sum.  Deterministic.
// Block: 16 q-lanes x 32 p-strips (512 thr). Grid: (TQ/16, B) = 128 blocks.
// ---------------------------------------------------------------------------
__global__ __launch_bounds__(512) void colsum_kernel() {
    __shared__ float red[32][17];

    const int b = blockIdx.y;
    const int tx = threadIdx.x & 15;
    const int ty = threadIdx.x >> 4;
    const int q = blockIdx.x * 16 + tx;
    const float* s = g_sc + (size_t)b * TP_ * TQ_ + q;

    float sum = 0.f;
#pragma unroll 8
    for (int p = ty; p < TP_; p += 32) sum += s[(size_t)p * TQ_];
    red[ty][tx] = sum;
    __syncthreads();
    if (ty == 0) {
        float ss = red[0][tx];
#pragma unroll
        for (int k = 1; k < 32; k++) ss += red[k][tx];
        g_inv[b * TQ_ + q] = __fdividef(1.0f, ss);
    }
}

// ---------------------------------------------------------------------------
// Kernel 4: out GEMM (tf32 TC), normalize fused into A load.
//   out[b] = (e[b] .* inv[b]) @ q[b],  per-b [512,512]x[512,256]
// grid (256/64, 512/64, 4) = 128 blocks.
// ---------------------------------------------------------------------------
__global__ __launch_bounds__(256) void out_gemm_kernel(const float* __restrict__ qin,
                                                       float* __restrict__ out) {
    const int b = blockIdx.z;
    tf32_gemm_64x64<true>(g_sc + (size_t)b * TP_ * TQ_,
                          qin + (size_t)b * TQ_ * D_,
                          out + (size_t)b * TP_ * D_,
                          g_inv + b * TQ_, D_, TQ_,
                          blockIdx.y * 64, blockIdx.x * 64);
}

// ---------------------------------------------------------------------------
// Launch
// ---------------------------------------------------------------------------
extern "C" void kernel_launch(void* const* d_in, const int* in_sizes, int n_in,
                              void* d_out, int out_size) {
    const float* q = (const float*)d_in[0];   // [B,Tq,D]
    const float* p = (const float*)d_in[1];   // [B,Tp,D]
    const float* W0 = (const float*)d_in[2];  // [D,D]
    const float* W1 = (const float*)d_in[3];  // [D,D]
    const float* vc = (const float*)d_in[4];  // [D,1]
    float* out = (float*)d_out;               // [B,Tp,D]

    // 1. Projections (tensor core, direct output)
    {
        dim3 grid(D_ / 64, (B_ * TQ_) / 64, 2);
        proj_kernel<<<grid, 256>>>(q, p, W0, W1);
    }
    // 2. Energies -> exp(score)
    {
        dim3 grid(TQ_ / 64, TP_ / 64, B_);
        energy_kernel<<<grid, 256>>>(vc);
    }
    // 3. Column sums -> inverse
    {
        dim3 grid(TQ_ / 16, B_);
        colsum_kernel<<<grid, 512>>>();
    }
    // 4. Output GEMM (tensor core, fused normalize, direct output)
    {
        dim3 grid(D_ / 64, TP_ / 64, B_);
        out_gemm_kernel<<<grid, 256>>>(q, out);
    }
}

// round 6
// speedup vs baseline: 2.3015x; 1.0122x over previous
#include <cuda_runtime.h>
#include <cuda_fp16.h>
#include <cuda_bf16.h>
#include <cstddef>
#include <cstdint>

// Problem constants
#define B_   4
#define TQ_  512
#define TP_  512
#define D_   256

// ---------------------------------------------------------------------------
// Scratch (static device globals)
// ---------------------------------------------------------------------------
__device__ float g_pq[(size_t)B_ * TQ_ * D_];    // q @ W0  [B,Tq,D]
__device__ float g_pp[(size_t)B_ * TP_ * D_];    // p @ W1  [B,Tp,D]
__device__ float g_sc[(size_t)B_ * TP_ * TQ_];   // exp(scores) [B,Tp,Tq]
__device__ float g_cpart[B_ * 8 * TQ_];          // per-p-tile column partial sums
__device__ float g_inv[B_ * TQ_];                // 1 / sum_p exp(score)
__device__ float g_part[2 * 1024 * 1024];        // 8MB split-K partials

// ---------------------------------------------------------------------------
// fp32 HW tanh (1 MUFU op) -- f16x2 variant measured at half rate, no gain.
// ---------------------------------------------------------------------------
__device__ __forceinline__ float ftanh(float x) {
    float r;
    asm("tanh.approx.f32 %0, %1;" : "=f"(r) : "f"(x));
    return r;
}

__device__ __forceinline__ uint32_t f2tf32(float x) {
    uint32_t r;
    asm("cvt.rna.tf32.f32 %0, %1;" : "=r"(r) : "f"(x));
    return r;
}

// ---------------------------------------------------------------------------
// tf32 tensor-core GEMM slice, 64x64 block tile, 256 threads (8 warps 2x4),
// warp tile 32x16 (2 m-frags x 2 n-frags of m16n8k8).
// C[M,N] (partial) = A[M, kbeg:kend] * B[kbeg:kend, N], both row-major.
// If SCALE, A column k is scaled by cs[k] at load.
// ---------------------------------------------------------------------------
template <bool SCALE>
__device__ __forceinline__ void tf32_gemm_64x64(const float* __restrict__ A,
                                                const float* __restrict__ B,
                                                float* __restrict__ C,
                                                const float* __restrict__ cs,
                                                int N, int K, int kbeg, int kend,
                                                int m0, int n0) {
    __shared__ uint32_t As[64][36];  // [m][k]
    __shared__ uint32_t Bs[32][72];  // [k][n]

    const int tid = threadIdx.x;
    const int lane = tid & 31;
    const int w = tid >> 5;
    const int wm = (w >> 2) * 32;
    const int wn = (w & 3) * 16;
    const int frow = lane >> 2;
    const int fcol = lane & 3;

    float c[2][2][4];
#pragma unroll
    for (int mi = 0; mi < 2; mi++)
#pragma unroll
        for (int ni = 0; ni < 2; ni++)
#pragma unroll
            for (int k = 0; k < 4; k++) c[mi][ni][k] = 0.0f;

    float4 ra[2], rb[2];
    auto loadG = [&](int k0) {
#pragma unroll
        for (int s = 0; s < 2; s++) {
            int id = tid + s * 256;
            int r = id >> 3, cc = (id & 7) * 4;
            ra[s] = *(const float4*)&A[(size_t)(m0 + r) * K + k0 + cc];
            if (SCALE) {
                float4 sc = *(const float4*)&cs[k0 + cc];
                ra[s].x *= sc.x; ra[s].y *= sc.y;
                ra[s].z *= sc.z; ra[s].w *= sc.w;
            }
        }
#pragma unroll
        for (int s = 0; s < 2; s++) {
            int id = tid + s * 256;
            int r = id >> 4, cc = (id & 15) * 4;
            rb[s] = *(const float4*)&B[(size_t)(k0 + r) * N + n0 + cc];
        }
    };
    auto storeS = [&]() {
#pragma unroll
        for (int s = 0; s < 2; s++) {
            int id = tid + s * 256;
            int r = id >> 3, cc = (id & 7) * 4;
            As[r][cc + 0] = f2tf32(ra[s].x);
            As[r][cc + 1] = f2tf32(ra[s].y);
            As[r][cc + 2] = f2tf32(ra[s].z);
            As[r][cc + 3] = f2tf32(ra[s].w);
        }
#pragma unroll
        for (int s = 0; s < 2; s++) {
            int id = tid + s * 256;
            int r = id >> 4, cc = (id & 15) * 4;
            Bs[r][cc + 0] = f2tf32(rb[s].x);
            Bs[r][cc + 1] = f2tf32(rb[s].y);
            Bs[r][cc + 2] = f2tf32(rb[s].z);
            Bs[r][cc + 3] = f2tf32(rb[s].w);
        }
    };

    loadG(kbeg);
    for (int k0 = kbeg; k0 < kend; k0 += 32) {
        storeS();
        __syncthreads();
        if (k0 + 32 < kend) loadG(k0 + 32);
#pragma unroll
        for (int ks = 0; ks < 4; ks++) {
            const int kk = ks * 8;
            uint32_t a[2][4], bfr[2][2];
#pragma unroll
            for (int mi = 0; mi < 2; mi++) {
                a[mi][0] = As[wm + mi * 16 + frow][kk + fcol];
                a[mi][1] = As[wm + mi * 16 + frow + 8][kk + fcol];
                a[mi][2] = As[wm + mi * 16 + frow][kk + fcol + 4];
                a[mi][3] = As[wm + mi * 16 + frow + 8][kk + fcol + 4];
            }
#pragma unroll
            for (int ni = 0; ni < 2; ni++) {
                bfr[ni][0] = Bs[kk + fcol][wn + ni * 8 + frow];
                bfr[ni][1] = Bs[kk + fcol + 4][wn + ni * 8 + frow];
            }
#pragma unroll
            for (int mi = 0; mi < 2; mi++)
#pragma unroll
                for (int ni = 0; ni < 2; ni++)
                    asm volatile(
                        "mma.sync.aligned.m16n8k8.row.col.f32.tf32.tf32.f32 "
                        "{%0,%1,%2,%3},{%4,%5,%6,%7},{%8,%9},{%0,%1,%2,%3};"
                        : "+f"(c[mi][ni][0]), "+f"(c[mi][ni][1]),
                          "+f"(c[mi][ni][2]), "+f"(c[mi][ni][3])
                        : "r"(a[mi][0]), "r"(a[mi][1]), "r"(a[mi][2]),
                          "r"(a[mi][3]), "r"(bfr[ni][0]), "r"(bfr[ni][1]));
        }
        __syncthreads();
    }

#pragma unroll
    for (int mi = 0; mi < 2; mi++)
#pragma unroll
        for (int ni = 0; ni < 2; ni++) {
            int rr = m0 + wm + mi * 16 + frow;
            int cc = n0 + wn + ni * 8 + fcol * 2;
            *(float2*)&C[(size_t)rr * N + cc] =
                make_float2(c[mi][ni][0], c[mi][ni][1]);
            *(float2*)&C[(size_t)(rr + 8) * N + cc] =
                make_float2(c[mi][ni][2], c[mi][ni][3]);
        }
}

// ---------------------------------------------------------------------------
// Kernel 1: projections (tf32 TC).  z: 0 -> g_pq = q@W0, 1 -> g_pp = p@W1.
// ---------------------------------------------------------------------------
__global__ __launch_bounds__(256) void proj_kernel(const float* __restrict__ q,
                                                   const float* __restrict__ p,
                                                   const float* __restrict__ W0,
                                                   const float* __restrict__ W1) {
    const int t = blockIdx.z;
    const float* A = t ? p : q;
    const float* Bw = t ? W1 : W0;
    float* C = t ? g_pp : g_pq;
    tf32_gemm_64x64<false>(A, Bw, C, nullptr, D_, D_, 0, D_,
                           blockIdx.y * 64, blockIdx.x * 64);
}

// ---------------------------------------------------------------------------
// Kernel 2: energies -> exp(score) + per-block column partial sums.
//   e[b,p,q] = exp( sum_d vc[d] * tanh(pp[b,p,d] + pq[b,q,d]) )
//   g_cpart[b][py][q] = sum over this block's 64 p-rows of e
// fp32 MUFU.TANH, 64x64 tile, 4x4 micro.  No max subtraction needed:
// |score| <= sum|vc| ~ 10, exp safe in fp32.
// ---------------------------------------------------------------------------
__global__ __launch_bounds__(256) void energy_kernel(const float* __restrict__ vc) {
    __shared__ float sp[64][33];
    __shared__ float sq[64][33];
    __shared__ float sv[32];
    __shared__ float colred[16][64];

    const int b = blockIdx.z;
    const int p0 = blockIdx.y * 64;
    const int q0 = blockIdx.x * 64;
    const int tid = threadIdx.x;
    const int tx = tid & 15;
    const int ty = tid >> 4;

    const float* ppb = g_pp + ((size_t)b * TP_ + p0) * D_;
    const float* pqb = g_pq + ((size_t)b * TQ_ + q0) * D_;

    float acc[4][4];
#pragma unroll
    for (int i = 0; i < 4; i++)
#pragma unroll
        for (int j = 0; j < 4; j++) acc[i][j] = 0.0f;

    for (int d0 = 0; d0 < D_; d0 += 32) {
        if (tid < 32) sv[tid] = vc[d0 + tid];
#pragma unroll
        for (int s = 0; s < 2; s++) {
            int id = tid + s * 256;
            int r = id >> 3, cc = (id & 7) * 4;
            float4 vP = *(const float4*)&ppb[(size_t)r * D_ + d0 + cc];
            float4 vQ = *(const float4*)&pqb[(size_t)r * D_ + d0 + cc];
            sp[r][cc + 0] = vP.x; sp[r][cc + 1] = vP.y;
            sp[r][cc + 2] = vP.z; sp[r][cc + 3] = vP.w;
            sq[r][cc + 0] = vQ.x; sq[r][cc + 1] = vQ.y;
            sq[r][cc + 2] = vQ.z; sq[r][cc + 3] = vQ.w;
        }
        __syncthreads();

#pragma unroll 8
        for (int d = 0; d < 32; d++) {
            float v = sv[d];
            float a[4], bb[4];
#pragma unroll
            for (int i = 0; i < 4; i++) a[i] = sp[ty * 4 + i][d];
#pragma unroll
            for (int j = 0; j < 4; j++) bb[j] = sq[tx * 4 + j][d];
#pragma unroll
            for (int i = 0; i < 4; i++)
#pragma unroll
                for (int j = 0; j < 4; j++)
                    acc[i][j] = fmaf(v, ftanh(a[i] + bb[j]), acc[i][j]);
        }
        __syncthreads();
    }

    // exp, write, and accumulate per-thread column partials
    float colp[4] = {0.f, 0.f, 0.f, 0.f};
#pragma unroll
    for (int i = 0; i < 4; i++) {
        float4 o;
        o.x = __expf(acc[i][0]);
        o.y = __expf(acc[i][1]);
        o.z = __expf(acc[i][2]);
        o.w = __expf(acc[i][3]);
        colp[0] += o.x; colp[1] += o.y; colp[2] += o.z; colp[3] += o.w;
        *(float4*)&g_sc[((size_t)b * TP_ + p0 + ty * 4 + i) * TQ_ + q0 + tx * 4] = o;
    }
    *(float4*)&colred[ty][tx * 4] =
        make_float4(colp[0], colp[1], colp[2], colp[3]);
    __syncthreads();
    if (tid < 64) {
        float s = colred[0][tid];
#pragma unroll
        for (int t = 1; t < 16; t++) s += colred[t][tid];
        g_cpart[(b * 8 + blockIdx.y) * TQ_ + q0 + tid] = s;
    }
}

// ---------------------------------------------------------------------------
// Kernel 3: reduce column partials -> g_inv.  8 blocks x 256 threads.
// ---------------------------------------------------------------------------
__global__ __launch_bounds__(256) void colsum_reduce_kernel() {
    const int i = blockIdx.x * 256 + threadIdx.x;  // [0, B*TQ)
    const int b = i >> 9;
    const int q = i & 511;
    float s = 0.f;
#pragma unroll
    for (int t = 0; t < 8; t++) s += g_cpart[(b * 8 + t) * TQ_ + q];
    g_inv[i] = __fdividef(1.0f, s);
}

// ---------------------------------------------------------------------------
// Kernel 4: out GEMM (tf32 TC), split-K=4, normalize fused into A load.
//   part[s*4+b] = (e[b] .* inv[b])[:, ks:ks+128] @ q[b][ks:ks+128, :]
// grid (4, 8, 16) = 512 blocks.
// ---------------------------------------------------------------------------
__global__ __launch_bounds__(256) void out_gemm_kernel(const float* __restrict__ qin) {
    const int b = blockIdx.z & 3;
    const int s = blockIdx.z >> 2;
    float* C = g_part + (size_t)(s * 4 + b) * (TP_ * D_);
    tf32_gemm_64x64<true>(g_sc + (size_t)b * TP_ * TQ_,
                          qin + (size_t)b * TQ_ * D_, C,
                          g_inv + b * TQ_, D_, TQ_,
                          s * 128, s * 128 + 128,
                          blockIdx.y * 64, blockIdx.x * 64);
}

// Reduce out partials: out = sum over 4 splits.  Deterministic.
__global__ __launch_bounds__(256) void out_reduce_kernel(float* __restrict__ out) {
    const int i = blockIdx.x * 256 + threadIdx.x;  // float4 idx
    constexpr int NB4 = (TP_ * D_) / 4;
    const int b = i / NB4;
    const int j = i % NB4;
    float4 r = make_float4(0.f, 0.f, 0.f, 0.f);
#pragma unroll
    for (int s = 0; s < 4; s++) {
        float4 v = *((const float4*)g_part + (size_t)(s * 4 + b) * NB4 + j);
        r.x += v.x; r.y += v.y; r.z += v.z; r.w += v.w;
    }
    *((float4*)out + i) = r;
}

// ---------------------------------------------------------------------------
// Launch
// ---------------------------------------------------------------------------
extern "C" void kernel_launch(void* const* d_in, const int* in_sizes, int n_in,
                              void* d_out, int out_size) {
    const float* q = (const float*)d_in[0];   // [B,Tq,D]
    const float* p = (const float*)d_in[1];   // [B,Tp,D]
    const float* W0 = (const float*)d_in[2];  // [D,D]
    const float* W1 = (const float*)d_in[3];  // [D,D]
    const float* vc = (const float*)d_in[4];  // [D,1]
    float* out = (float*)d_out;               // [B,Tp,D]

    // 1. Projections (tensor core, direct output)
    {
        dim3 grid(D_ / 64, (B_ * TQ_) / 64, 2);
        proj_kernel<<<grid, 256>>>(q, p, W0, W1);
    }
    // 2. Energies -> exp(score) + column partials
    {
        dim3 grid(TQ_ / 64, TP_ / 64, B_);
        energy_kernel<<<grid, 256>>>(vc);
    }
    // 3. Column partial reduce -> inverse
    {
        colsum_reduce_kernel<<<(B_ * TQ_) / 256, 256>>>();
    }
    // 4. Output GEMM (tensor core, split-K=4, fused normalize) + reduce
    {
        dim3 grid(D_ / 64, TP_ / 64, 16);
        out_gemm_kernel<<<grid, 256>>>(q);
        out_reduce_kernel<<<(B_ * TP_ * D_ / 4) / 256, 256>>>(out);
    }
}